// round 14
// baseline (speedup 1.0000x reference)
#include <cuda_runtime.h>
#include <cuda_fp16.h>
#include <cstdint>

// STN flow-relative bilinear warp, two-pass with fp16 NHWC scratch:
//   pass 1: NCHW f32 -> NHWC fp16 scratch (uint4 phase-2 stores)
//   pass 2: cooperative gather (4 lanes/pixel, adjacent pixel pair per
//           thread, hoisted offsets + front-batched loads) with float2 NCHW
//           stores.  R13 body + __launch_bounds__(256,6) ONLY.

static constexpr int H  = 1024;
static constexpr int W  = 1024;
static constexpr int C  = 32;
static constexpr int HW = H * W;

// 64 MB scratch: x transposed to [H*W][C] in fp16 (mostly L2-resident)
__device__ __half g_xt[(size_t)HW * C];

// ---------------- pass 1: NCHW -> NHWC transpose + f32->fp16 ----------------
__device__ __forceinline__ int sw_addr(int c, int px) {
    return c * 128 + 4 * ((px >> 2) ^ (c >> 2)) + (px & 3);
}

__global__ __launch_bounds__(256) void transpose_kernel(const float* __restrict__ x)
{
    __shared__ float s[32 * 128];

    int tid = threadIdx.x;
    int p0  = blockIdx.x * 128;

#pragma unroll
    for (int i = 0; i < 4; ++i) {
        int j   = i * 256 + tid;
        int c   = j >> 5;
        int pxg = j & 31;
        float4 v = __ldcs((const float4*)(x + (size_t)c * HW + p0 + 4 * pxg));
        *(float4*)(s + c * 128 + 4 * (pxg ^ (c >> 2))) = v;
    }
    __syncthreads();

#pragma unroll
    for (int i = 0; i < 2; ++i) {
        int j  = i * 256 + tid;
        int pl = j >> 2;           // pixel 0..127
        int cg = j & 3;            // channel octet 0..3 (8 channels)
        int c0 = 8 * cg;
        __half2 h0 = __floats2half2_rn(s[sw_addr(c0 + 0, pl)], s[sw_addr(c0 + 1, pl)]);
        __half2 h1 = __floats2half2_rn(s[sw_addr(c0 + 2, pl)], s[sw_addr(c0 + 3, pl)]);
        __half2 h2 = __floats2half2_rn(s[sw_addr(c0 + 4, pl)], s[sw_addr(c0 + 5, pl)]);
        __half2 h3 = __floats2half2_rn(s[sw_addr(c0 + 6, pl)], s[sw_addr(c0 + 7, pl)]);
        uint4 v;
        v.x = *(const unsigned int*)&h0;
        v.y = *(const unsigned int*)&h1;
        v.z = *(const unsigned int*)&h2;
        v.w = *(const unsigned int*)&h3;
        *(uint4*)(g_xt + (size_t)(p0 + pl) * C + 8 * cg) = v;
    }
}

// ---------------- pass 2: bilinear warp from fp16 NHWC ----------------
// Block = 256 threads, 128 pixels. Thread = (pixel-pair, channel-octet):
// pixels 2*pl and 2*pl+1 (adjacent) -> float2 stores.
__global__ __launch_bounds__(256, 6) void warp_bilinear_coop_kernel(
    const float* __restrict__ flow,
    float* __restrict__ out)
{
    __shared__ int   s_off[4][128];
    __shared__ float s_w[4][128];

    int tid = threadIdx.x;
    int p0  = blockIdx.x * 128;

    if (tid < 128) {
        int p  = p0 + tid;
        int px = p & (W - 1);
        int py = p >> 10;              // W == 1024

        float fx = flow[p];
        float fy = flow[HW + p];

        // Match reference math exactly (normalize + unnormalize round-trip)
        float gx = (fx + (float)px) * (2.0f / (float)(W - 1)) - 1.0f;
        float gy = (fy + (float)py) * (2.0f / (float)(H - 1)) - 1.0f;
        float ix = ((gx + 1.0f) * (float)W - 1.0f) * 0.5f;
        float iy = ((gy + 1.0f) * (float)H - 1.0f) * 0.5f;

        float x0f = floorf(ix);
        float y0f = floorf(iy);
        float wx1 = ix - x0f;
        float wy1 = iy - y0f;
        float wx0 = 1.0f - wx1;
        float wy0 = 1.0f - wy1;

        int x0 = (int)x0f;
        int y0 = (int)y0f;
        int x1 = x0 + 1;
        int y1 = y0 + 1;

        float vx0 = (x0 >= 0 && x0 < W) ? 1.0f : 0.0f;
        float vx1 = (x1 >= 0 && x1 < W) ? 1.0f : 0.0f;
        float vy0 = (y0 >= 0 && y0 < H) ? 1.0f : 0.0f;
        float vy1 = (y1 >= 0 && y1 < H) ? 1.0f : 0.0f;

        int cx0 = min(max(x0, 0), W - 1);
        int cx1 = min(max(x1, 0), W - 1);
        int cy0 = min(max(y0, 0), H - 1);
        int cy1 = min(max(y1, 0), H - 1);

        s_w[0][tid] = wx0 * wy0 * vx0 * vy0;
        s_w[1][tid] = wx1 * wy0 * vx1 * vy0;
        s_w[2][tid] = wx0 * wy1 * vx0 * vy1;
        s_w[3][tid] = wx1 * wy1 * vx1 * vy1;

        s_off[0][tid] = cy0 * W + cx0;
        s_off[1][tid] = cy0 * W + cx1;
        s_off[2][tid] = cy1 * W + cx0;
        s_off[3][tid] = cy1 * W + cx1;
    }
    __syncthreads();

    int pl = tid >> 2;                 // 0..63 -> pixels 2*pl, 2*pl+1
    int cg = tid & 3;                  // channel octet (0..3), 8 halves each

    // hoist all smem reads, then front-batch the corner loads
    int   off[2][4];
    float wgt[2][4];
#pragma unroll
    for (int half = 0; half < 2; ++half) {
        int pp = 2 * pl + half;
#pragma unroll
        for (int k = 0; k < 4; ++k) {
            off[half][k] = s_off[k][pp];
            wgt[half][k] = s_w[k][pp];
        }
    }

    uint4 v[2][4];
#pragma unroll
    for (int half = 0; half < 2; ++half)
#pragma unroll
        for (int k = 0; k < 4; ++k)
            v[half][k] = __ldg((const uint4*)(g_xt + (size_t)off[half][k] * C) + cg);

    float a[2][8];
#pragma unroll
    for (int half = 0; half < 2; ++half) {
#pragma unroll
        for (int j = 0; j < 8; ++j) a[half][j] = 0.f;
#pragma unroll
        for (int k = 0; k < 4; ++k) {
            float w = wgt[half][k];
            float2 f0 = __half22float2(*(const __half2*)&v[half][k].x);
            float2 f1 = __half22float2(*(const __half2*)&v[half][k].y);
            float2 f2 = __half22float2(*(const __half2*)&v[half][k].z);
            float2 f3 = __half22float2(*(const __half2*)&v[half][k].w);
            a[half][0] += w * f0.x;  a[half][1] += w * f0.y;
            a[half][2] += w * f1.x;  a[half][3] += w * f1.y;
            a[half][4] += w * f2.x;  a[half][5] += w * f2.y;
            a[half][6] += w * f3.x;  a[half][7] += w * f3.y;
        }
    }

    // float2 NCHW stores: channel 8*cg+j, adjacent pixel pair 2*pl..2*pl+1.
    float* ob = out + (size_t)(cg * 8) * HW + p0 + 2 * pl;
#pragma unroll
    for (int j = 0; j < 8; ++j) {
        float2 st = make_float2(a[0][j], a[1][j]);
        __stcs((float2*)(ob + (size_t)j * HW), st);
    }
}

extern "C" void kernel_launch(void* const* d_in, const int* in_sizes, int n_in,
                              void* d_out, int out_size)
{
    const float* flow = (const float*)d_in[0];   // [1,2,H,W]
    const float* x    = (const float*)d_in[1];   // [1,C,H,W]
    float* out        = (float*)d_out;           // [1,C,H,W]

    (void)in_sizes; (void)n_in; (void)out_size;

    transpose_kernel<<<HW / 128, 256>>>(x);
    warp_bilinear_coop_kernel<<<HW / 128, 256>>>(flow, out);
}

// round 15
// speedup vs baseline: 1.0426x; 1.0426x over previous
#include <cuda_runtime.h>
#include <cuda_fp16.h>
#include <cstdint>

// STN flow-relative bilinear warp, two-pass with fp16 NHWC scratch:
//   pass 1: NCHW f32 -> NHWC fp16 scratch, 256-px tiles (MLP=8 loads,
//           two independent 128-px swizzled smem subtiles)
//   pass 2: cooperative gather (4 lanes/pixel, adjacent pixel pair per
//           thread, MLP=8 front-batch, 48 regs) with float2 NCHW stores.
//           [R13 verbatim -- proven 44.7us]

static constexpr int H  = 1024;
static constexpr int W  = 1024;
static constexpr int C  = 32;
static constexpr int HW = H * W;

// 64 MB scratch: x transposed to [H*W][C] in fp16 (mostly L2-resident)
__device__ __half g_xt[(size_t)HW * C];

// ---------------- pass 1: NCHW -> NHWC transpose + f32->fp16 ----------------
__device__ __forceinline__ int sw_addr(int c, int px) {
    return c * 128 + 4 * ((px >> 2) ^ (c >> 2)) + (px & 3);
}

// Block: 256 threads, tile = 256 pixels x 32 channels (two 128-px subtiles).
__global__ __launch_bounds__(256) void transpose_kernel(const float* __restrict__ x)
{
    __shared__ float s[2 * 32 * 128];          // 32 KB: two swizzled subtiles

    int tid = threadIdx.x;
    int p0  = blockIdx.x * 256;

    // phase 1: 8 front-batched float4 reads per thread (coalesced, streaming)
    float4 v[8];
#pragma unroll
    for (int i = 0; i < 8; ++i) {
        int j   = i * 256 + tid;
        int sub = j >> 10;         // 0..1: which 128-px subtile
        int jj  = j & 1023;
        int c   = jj >> 5;         // 0..31
        int pxg = jj & 31;         // quad index within subtile
        v[i] = __ldcs((const float4*)(x + (size_t)c * HW + p0 + sub * 128 + 4 * pxg));
    }
#pragma unroll
    for (int i = 0; i < 8; ++i) {
        int j   = i * 256 + tid;
        int sub = j >> 10;
        int jj  = j & 1023;
        int c   = jj >> 5;
        int pxg = jj & 31;
        *(float4*)(s + sub * 4096 + c * 128 + 4 * (pxg ^ (c >> 2))) = v[i];
    }
    __syncthreads();

    // phase 2: 8 channels/thread -> uint4 (16B) NHWC store; 4 iterations
#pragma unroll
    for (int i = 0; i < 4; ++i) {
        int j   = i * 256 + tid;
        int pl  = j >> 2;          // pixel 0..255
        int cg  = j & 3;           // channel octet 0..3
        int sub = pl >> 7;
        int plo = pl & 127;
        const float* sb = s + sub * 4096;
        int c0 = 8 * cg;
        __half2 h0 = __floats2half2_rn(sb[sw_addr(c0 + 0, plo)], sb[sw_addr(c0 + 1, plo)]);
        __half2 h1 = __floats2half2_rn(sb[sw_addr(c0 + 2, plo)], sb[sw_addr(c0 + 3, plo)]);
        __half2 h2 = __floats2half2_rn(sb[sw_addr(c0 + 4, plo)], sb[sw_addr(c0 + 5, plo)]);
        __half2 h3 = __floats2half2_rn(sb[sw_addr(c0 + 6, plo)], sb[sw_addr(c0 + 7, plo)]);
        uint4 o;
        o.x = *(const unsigned int*)&h0;
        o.y = *(const unsigned int*)&h1;
        o.z = *(const unsigned int*)&h2;
        o.w = *(const unsigned int*)&h3;
        *(uint4*)(g_xt + (size_t)(p0 + pl) * C + 8 * cg) = o;
    }
}

// ---------------- pass 2: bilinear warp from fp16 NHWC (R13 verbatim) -------
// Block = 256 threads, 128 pixels. Thread = (pixel-pair, channel-octet):
// pixels 2*pl and 2*pl+1 (adjacent) -> float2 stores.
__global__ __launch_bounds__(256) void warp_bilinear_coop_kernel(
    const float* __restrict__ flow,
    float* __restrict__ out)
{
    __shared__ int   s_off[4][128];
    __shared__ float s_w[4][128];

    int tid = threadIdx.x;
    int p0  = blockIdx.x * 128;

    if (tid < 128) {
        int p  = p0 + tid;
        int px = p & (W - 1);
        int py = p >> 10;              // W == 1024

        float fx = flow[p];
        float fy = flow[HW + p];

        // Match reference math exactly (normalize + unnormalize round-trip)
        float gx = (fx + (float)px) * (2.0f / (float)(W - 1)) - 1.0f;
        float gy = (fy + (float)py) * (2.0f / (float)(H - 1)) - 1.0f;
        float ix = ((gx + 1.0f) * (float)W - 1.0f) * 0.5f;
        float iy = ((gy + 1.0f) * (float)H - 1.0f) * 0.5f;

        float x0f = floorf(ix);
        float y0f = floorf(iy);
        float wx1 = ix - x0f;
        float wy1 = iy - y0f;
        float wx0 = 1.0f - wx1;
        float wy0 = 1.0f - wy1;

        int x0 = (int)x0f;
        int y0 = (int)y0f;
        int x1 = x0 + 1;
        int y1 = y0 + 1;

        float vx0 = (x0 >= 0 && x0 < W) ? 1.0f : 0.0f;
        float vx1 = (x1 >= 0 && x1 < W) ? 1.0f : 0.0f;
        float vy0 = (y0 >= 0 && y0 < H) ? 1.0f : 0.0f;
        float vy1 = (y1 >= 0 && y1 < H) ? 1.0f : 0.0f;

        int cx0 = min(max(x0, 0), W - 1);
        int cx1 = min(max(x1, 0), W - 1);
        int cy0 = min(max(y0, 0), H - 1);
        int cy1 = min(max(y1, 0), H - 1);

        s_w[0][tid] = wx0 * wy0 * vx0 * vy0;
        s_w[1][tid] = wx1 * wy0 * vx1 * vy0;
        s_w[2][tid] = wx0 * wy1 * vx0 * vy1;
        s_w[3][tid] = wx1 * wy1 * vx1 * vy1;

        s_off[0][tid] = cy0 * W + cx0;
        s_off[1][tid] = cy0 * W + cx1;
        s_off[2][tid] = cy1 * W + cx0;
        s_off[3][tid] = cy1 * W + cx1;
    }
    __syncthreads();

    int pl = tid >> 2;                 // 0..63 -> pixels 2*pl, 2*pl+1
    int cg = tid & 3;                  // channel octet (0..3), 8 halves each

    // hoist all smem reads, then front-batch ALL 8 corner loads (MLP=8)
    int   off[2][4];
    float wgt[2][4];
#pragma unroll
    for (int half = 0; half < 2; ++half) {
        int pp = 2 * pl + half;
#pragma unroll
        for (int k = 0; k < 4; ++k) {
            off[half][k] = s_off[k][pp];
            wgt[half][k] = s_w[k][pp];
        }
    }

    uint4 v[2][4];
#pragma unroll
    for (int half = 0; half < 2; ++half)
#pragma unroll
        for (int k = 0; k < 4; ++k)
            v[half][k] = __ldg((const uint4*)(g_xt + (size_t)off[half][k] * C) + cg);

    float a[2][8];
#pragma unroll
    for (int half = 0; half < 2; ++half) {
#pragma unroll
        for (int j = 0; j < 8; ++j) a[half][j] = 0.f;
#pragma unroll
        for (int k = 0; k < 4; ++k) {
            float w = wgt[half][k];
            float2 f0 = __half22float2(*(const __half2*)&v[half][k].x);
            float2 f1 = __half22float2(*(const __half2*)&v[half][k].y);
            float2 f2 = __half22float2(*(const __half2*)&v[half][k].z);
            float2 f3 = __half22float2(*(const __half2*)&v[half][k].w);
            a[half][0] += w * f0.x;  a[half][1] += w * f0.y;
            a[half][2] += w * f1.x;  a[half][3] += w * f1.y;
            a[half][4] += w * f2.x;  a[half][5] += w * f2.y;
            a[half][6] += w * f3.x;  a[half][7] += w * f3.y;
        }
    }

    // float2 NCHW stores: channel 8*cg+j, adjacent pixel pair 2*pl..2*pl+1.
    float* ob = out + (size_t)(cg * 8) * HW + p0 + 2 * pl;
#pragma unroll
    for (int j = 0; j < 8; ++j) {
        float2 st = make_float2(a[0][j], a[1][j]);
        __stcs((float2*)(ob + (size_t)j * HW), st);
    }
}

extern "C" void kernel_launch(void* const* d_in, const int* in_sizes, int n_in,
                              void* d_out, int out_size)
{
    const float* flow = (const float*)d_in[0];   // [1,2,H,W]
    const float* x    = (const float*)d_in[1];   // [1,C,H,W]
    float* out        = (float*)d_out;           // [1,C,H,W]

    (void)in_sizes; (void)n_in; (void)out_size;

    transpose_kernel<<<HW / 256, 256>>>(x);
    warp_bilinear_coop_kernel<<<HW / 128, 256>>>(flow, out);
}

// round 16
// speedup vs baseline: 1.1600x; 1.1125x over previous
#include <cuda_runtime.h>
#include <cuda_fp16.h>
#include <cstdint>

// STN flow-relative bilinear warp, two-pass with fp16 NHWC scratch:
//   pass 1: NCHW f32 -> NHWC fp16 scratch (R13 proven version)
//   pass 2: barrier-free cooperative gather: each thread redundantly computes
//           setup for its own adjacent pixel pair (no smem, no __syncthreads),
//           front-batched MLP=8 gather, float2 NCHW stores.

static constexpr int H  = 1024;
static constexpr int W  = 1024;
static constexpr int C  = 32;
static constexpr int HW = H * W;

// 64 MB scratch: x transposed to [H*W][C] in fp16 (mostly L2-resident)
__device__ __half g_xt[(size_t)HW * C];

// ---------------- pass 1: NCHW -> NHWC transpose + f32->fp16 ----------------
__device__ __forceinline__ int sw_addr(int c, int px) {
    return c * 128 + 4 * ((px >> 2) ^ (c >> 2)) + (px & 3);
}

__global__ __launch_bounds__(256) void transpose_kernel(const float* __restrict__ x)
{
    __shared__ float s[32 * 128];

    int tid = threadIdx.x;
    int p0  = blockIdx.x * 128;

#pragma unroll
    for (int i = 0; i < 4; ++i) {
        int j   = i * 256 + tid;
        int c   = j >> 5;
        int pxg = j & 31;
        float4 v = __ldcs((const float4*)(x + (size_t)c * HW + p0 + 4 * pxg));
        *(float4*)(s + c * 128 + 4 * (pxg ^ (c >> 2))) = v;
    }
    __syncthreads();

#pragma unroll
    for (int i = 0; i < 2; ++i) {
        int j  = i * 256 + tid;
        int pl = j >> 2;           // pixel 0..127
        int cg = j & 3;            // channel octet 0..3 (8 channels)
        int c0 = 8 * cg;
        __half2 h0 = __floats2half2_rn(s[sw_addr(c0 + 0, pl)], s[sw_addr(c0 + 1, pl)]);
        __half2 h1 = __floats2half2_rn(s[sw_addr(c0 + 2, pl)], s[sw_addr(c0 + 3, pl)]);
        __half2 h2 = __floats2half2_rn(s[sw_addr(c0 + 4, pl)], s[sw_addr(c0 + 5, pl)]);
        __half2 h3 = __floats2half2_rn(s[sw_addr(c0 + 6, pl)], s[sw_addr(c0 + 7, pl)]);
        uint4 v;
        v.x = *(const unsigned int*)&h0;
        v.y = *(const unsigned int*)&h1;
        v.z = *(const unsigned int*)&h2;
        v.w = *(const unsigned int*)&h3;
        *(uint4*)(g_xt + (size_t)(p0 + pl) * C + 8 * cg) = v;
    }
}

// ---------------- pass 2: barrier-free bilinear warp from fp16 NHWC ---------
// Block = 256 threads, 128 pixels. Thread = (pixel-pair, channel-octet):
// pixels 2*pl, 2*pl+1. Setup computed redundantly by the 4 threads sharing a
// pixel pair (no smem exchange, no syncs).
__global__ __launch_bounds__(256) void warp_bilinear_coop_kernel(
    const float* __restrict__ flow,
    float* __restrict__ out)
{
    int tid = threadIdx.x;
    int p0  = blockIdx.x * 128;

    int pl = tid >> 2;                 // 0..63 -> pixels 2*pl, 2*pl+1
    int cg = tid & 3;                  // channel octet (0..3), 8 halves each
    int pbase = p0 + 2 * pl;

    // flow loads: 4 lanes of each pixel-pair share one 8B load (broadcast)
    float2 fx2 = __ldg((const float2*)(flow + pbase));
    float2 fy2 = __ldg((const float2*)(flow + HW + pbase));

    int   off[2][4];
    float wgt[2][4];
#pragma unroll
    for (int half = 0; half < 2; ++half) {
        int p  = pbase + half;
        int px = p & (W - 1);
        int py = p >> 10;              // W == 1024

        float fx = half ? fx2.y : fx2.x;
        float fy = half ? fy2.y : fy2.x;

        // Match reference math exactly (normalize + unnormalize round-trip)
        float gx = (fx + (float)px) * (2.0f / (float)(W - 1)) - 1.0f;
        float gy = (fy + (float)py) * (2.0f / (float)(H - 1)) - 1.0f;
        float ix = ((gx + 1.0f) * (float)W - 1.0f) * 0.5f;
        float iy = ((gy + 1.0f) * (float)H - 1.0f) * 0.5f;

        float x0f = floorf(ix);
        float y0f = floorf(iy);
        float wx1 = ix - x0f;
        float wy1 = iy - y0f;
        float wx0 = 1.0f - wx1;
        float wy0 = 1.0f - wy1;

        int x0 = (int)x0f;
        int y0 = (int)y0f;
        int x1 = x0 + 1;
        int y1 = y0 + 1;

        float vx0 = (x0 >= 0 && x0 < W) ? 1.0f : 0.0f;
        float vx1 = (x1 >= 0 && x1 < W) ? 1.0f : 0.0f;
        float vy0 = (y0 >= 0 && y0 < H) ? 1.0f : 0.0f;
        float vy1 = (y1 >= 0 && y1 < H) ? 1.0f : 0.0f;

        int cx0 = min(max(x0, 0), W - 1);
        int cx1 = min(max(x1, 0), W - 1);
        int cy0 = min(max(y0, 0), H - 1);
        int cy1 = min(max(y1, 0), H - 1);

        wgt[half][0] = wx0 * wy0 * vx0 * vy0;
        wgt[half][1] = wx1 * wy0 * vx1 * vy0;
        wgt[half][2] = wx0 * wy1 * vx0 * vy1;
        wgt[half][3] = wx1 * wy1 * vx1 * vy1;

        off[half][0] = cy0 * W + cx0;
        off[half][1] = cy0 * W + cx1;
        off[half][2] = cy1 * W + cx0;
        off[half][3] = cy1 * W + cx1;
    }

    // front-batch ALL 8 corner loads (MLP=8)
    uint4 v[2][4];
#pragma unroll
    for (int half = 0; half < 2; ++half)
#pragma unroll
        for (int k = 0; k < 4; ++k)
            v[half][k] = __ldg((const uint4*)(g_xt + (size_t)off[half][k] * C) + cg);

    float a[2][8];
#pragma unroll
    for (int half = 0; half < 2; ++half) {
#pragma unroll
        for (int j = 0; j < 8; ++j) a[half][j] = 0.f;
#pragma unroll
        for (int k = 0; k < 4; ++k) {
            float w = wgt[half][k];
            float2 f0 = __half22float2(*(const __half2*)&v[half][k].x);
            float2 f1 = __half22float2(*(const __half2*)&v[half][k].y);
            float2 f2 = __half22float2(*(const __half2*)&v[half][k].z);
            float2 f3 = __half22float2(*(const __half2*)&v[half][k].w);
            a[half][0] += w * f0.x;  a[half][1] += w * f0.y;
            a[half][2] += w * f1.x;  a[half][3] += w * f1.y;
            a[half][4] += w * f2.x;  a[half][5] += w * f2.y;
            a[half][6] += w * f3.x;  a[half][7] += w * f3.y;
        }
    }

    // float2 NCHW stores: channel 8*cg+j, adjacent pixel pair 2*pl..2*pl+1.
    float* ob = out + (size_t)(cg * 8) * HW + pbase;
#pragma unroll
    for (int j = 0; j < 8; ++j) {
        float2 st = make_float2(a[0][j], a[1][j]);
        __stcs((float2*)(ob + (size_t)j * HW), st);
    }
}

extern "C" void kernel_launch(void* const* d_in, const int* in_sizes, int n_in,
                              void* d_out, int out_size)
{
    const float* flow = (const float*)d_in[0];   // [1,2,H,W]
    const float* x    = (const float*)d_in[1];   // [1,C,H,W]
    float* out        = (float*)d_out;           // [1,C,H,W]

    (void)in_sizes; (void)n_in; (void)out_size;

    transpose_kernel<<<HW / 128, 256>>>(x);
    warp_bilinear_coop_kernel<<<HW / 128, 256>>>(flow, out);
}